// round 5
// baseline (speedup 1.0000x reference)
#include <cuda_runtime.h>
#include <cuda_bf16.h>
#include <cstdint>

// ---------------- problem constants ----------------
#define N_PIX   65536
#define CDIM    64
#define KCODES  512
#define HWSZ    4096
#define CHW     (CDIM * HWSZ)

#define OUT_Q_ELEMS  (N_PIX * CDIM)
#define OUT_LOSS_OFF OUT_Q_ELEMS
#define OUT_PERP_OFF (OUT_Q_ELEMS + 1)
#define OUT_ACT_OFF  (OUT_Q_ELEMS + 2)
#define OUT_IDX_OFF  (OUT_Q_ELEMS + 3)

#define TILE_P  128
#define NBLK    (N_PIX / TILE_P)       // 512
#define NCHUNK  8                      // 8 x 64 codes
#define EPS     2.5f                   // cert window: > 2*(mma err 0.9 + enc err 0.08)

// ---------------- device scratch ----------------
__device__ __align__(16) uint16_t g_Bhi[KCODES * CDIM];
__device__ __align__(16) uint16_t g_Blo[KCODES * CDIM];
__device__ __align__(16) float    g_en2[KCODES];
__device__ int   g_hist[KCODES];
__device__ float g_part[NBLK];

// ---------------- smem layout ----------------
#define OFF_A     0          // 16384  A (bf16 of -2x), 128 rows x 128B
#define OFF_B_HI  16384      // 8192
#define OFF_B_LO  24576      // 8192
#define OFF_EN2   32768      // 2048
#define OFF_TOPV  34816      // 1536   128 rows x 3 floats (idx packed)
#define OFF_HIST  36352      // 2048
#define OFF_WS    38400      // 128
#define SMEM_MAIN 38528

// ---------------- PTX helpers (compute_103-legal only) ----------------
__device__ __forceinline__ uint32_t s2u(const void* p) {
    uint32_t a;
    asm("{ .reg .u64 t; cvta.to.shared.u64 t, %1; cvt.u32.u64 %0, t; }"
        : "=r"(a) : "l"(p));
    return a;
}
__device__ __forceinline__ void ldsm_x4(uint32_t& r0, uint32_t& r1,
                                        uint32_t& r2, uint32_t& r3, uint32_t a) {
    asm volatile("ldmatrix.sync.aligned.m8n8.x4.shared.b16 {%0,%1,%2,%3}, [%4];"
                 : "=r"(r0), "=r"(r1), "=r"(r2), "=r"(r3) : "r"(a));
}
__device__ __forceinline__ void mma_bf16(float& c0, float& c1, float& c2, float& c3,
                                         uint32_t a0, uint32_t a1, uint32_t a2, uint32_t a3,
                                         uint32_t b0, uint32_t b1) {
    asm volatile(
        "mma.sync.aligned.m16n8k16.row.col.f32.bf16.bf16.f32 "
        "{%0,%1,%2,%3}, {%4,%5,%6,%7}, {%8,%9}, {%0,%1,%2,%3};"
        : "+f"(c0), "+f"(c1), "+f"(c2), "+f"(c3)
        : "r"(a0), "r"(a1), "r"(a2), "r"(a3), "r"(b0), "r"(b1));
}

// pack code index into 9 low mantissa bits; fmin then carries the index for free
__device__ __forceinline__ float encd(float d, int k) {
    return __uint_as_float((__float_as_uint(d) & ~511u) | (uint32_t)k);
}
__device__ __forceinline__ int decd(float v) {
    return (int)(__float_as_uint(v) & 511u);
}
// branchless sorted-triple insert: 5 FMNMX, no predicates
__device__ __forceinline__ void ins3(float d, float& m1, float& m2, float& m3) {
    float t  = fmaxf(m1, d);
    m1 = fminf(m1, d);
    float t2 = fmaxf(m2, t);
    m2 = fminf(m2, t);
    m3 = fminf(m3, t2);
}

__device__ __forceinline__ float exact_dist(const float* __restrict__ xp,
                                            const float* __restrict__ emb,
                                            float en2v, int k) {
    const float4* er = (const float4*)(emb + (k << 6));
    float s0 = 0.f, s1 = 0.f, s2 = 0.f, s3 = 0.f;
    #pragma unroll
    for (int c4 = 0; c4 < 16; c4++) {
        float4 e4 = er[c4];
        s0 = fmaf(xp[(c4 * 4 + 0) * HWSZ], e4.x, s0);
        s1 = fmaf(xp[(c4 * 4 + 1) * HWSZ], e4.y, s1);
        s2 = fmaf(xp[(c4 * 4 + 2) * HWSZ], e4.z, s2);
        s3 = fmaf(xp[(c4 * 4 + 3) * HWSZ], e4.w, s3);
    }
    return fmaf(-2.0f, (s0 + s1) + (s2 + s3), en2v);
}

// ---------------- prep: bf16-split codebook + parallel en2 + zero hist ----------------
extern "C" __global__ void vq_prep(const float* __restrict__ emb) {
    __shared__ float ws[8];
    const int tid = threadIdx.x;
    const int idx = blockIdx.x * 256 + tid;           // 128 blocks x 256 = 32768
    float e = emb[idx];
    __nv_bfloat16 hi = __float2bfloat16(e);
    __nv_bfloat16 lo = __float2bfloat16(e - __bfloat162float(hi));
    g_Bhi[idx] = __bfloat16_as_ushort(hi);
    g_Blo[idx] = __bfloat16_as_ushort(lo);
    // en2: block covers 4 codes (64 ch each = 2 warps); shuffle-reduce
    float v = e * e;
    #pragma unroll
    for (int o = 16; o; o >>= 1) v += __shfl_xor_sync(0xffffffffu, v, o);
    if ((tid & 31) == 0) ws[tid >> 5] = v;
    __syncthreads();
    if (tid < 4) g_en2[blockIdx.x * 4 + tid] = ws[2 * tid] + ws[2 * tid + 1];
    if (blockIdx.x < 2) g_hist[blockIdx.x * 256 + tid] = 0;
}

// ---------------- main ----------------
extern "C" __global__ void __launch_bounds__(256, 4)
vq_main(const float* __restrict__ in, const float* __restrict__ emb,
        float* __restrict__ out)
{
    extern __shared__ char smc[];
    const uint32_t sb = s2u(smc);
    const int tid  = threadIdx.x;
    const int lane = tid & 31;
    const int wid  = tid >> 5;

    int*   histS = (int*)(smc + OFF_HIST);
    float* en2s  = (float*)(smc + OFF_EN2);
    float* topv  = (float*)(smc + OFF_TOPV);

    histS[tid] = 0; histS[tid + 256] = 0;
    if (tid < 128) ((float4*)en2s)[tid] = ((const float4*)g_en2)[tid];

    const int pbase = blockIdx.x * TILE_P;

    // ---- stage A: bf16(-2x), 128B swizzled rows ----
    {
        const int px = tid & 127;
        const int cb = (tid >> 7) * 32;
        const int p  = pbase + px;
        const float* xp = in + (p >> 12) * CHW + (p & (HWSZ - 1));
        #pragma unroll
        for (int c = cb; c < cb + 32; c += 2) {
            __nv_bfloat16 h0 = __float2bfloat16(-2.0f * xp[c * HWSZ]);
            __nv_bfloat16 h1 = __float2bfloat16(-2.0f * xp[(c + 1) * HWSZ]);
            uint32_t hp = (uint32_t)__bfloat16_as_ushort(h0) |
                          ((uint32_t)__bfloat16_as_ushort(h1) << 16);
            int col = (c * 2) ^ ((px & 7) * 16);
            *(uint32_t*)(smc + OFF_A + px * 128 + col) = hp;
        }
    }
    __syncthreads();

    // ---- resident A fragments: warp owns pixel rows 16*wid..+15 ----
    uint32_t Ah[4][4];
    {
        const int mtx = lane >> 3;
        const int r   = 16 * wid + (mtx & 1) * 8 + (lane & 7);
        const int kh  = (mtx >> 1) * 16;
        #pragma unroll
        for (int ks = 0; ks < 4; ks++) {
            int col = (ks * 32 + kh) ^ ((r & 7) * 16);
            ldsm_x4(Ah[ks][0], Ah[ks][1], Ah[ks][2], Ah[ks][3],
                    sb + OFF_A + r * 128 + col);
        }
    }

    // ---- sweep: 8 chunks x (4 j-pairs); top-3 via FMNMX, idx packed ----
    float m1a = 3.4e38f, m2a = 3.4e38f, m3a = 3.4e38f;   // row r
    float m1b = 3.4e38f, m2b = 3.4e38f, m3b = 3.4e38f;   // row r+8

    // B ldsm lane mapping: tile=(lane>>4)&1, khalf=(lane>>3)&1, row=lane&7
    const int btile  = (lane >> 4) & 1;
    const int bkhalf = ((lane >> 3) & 1) * 16;
    const int brow   = lane & 7;

    for (int ch = 0; ch < NCHUNK; ch++) {
        __syncthreads();
        {   // stage B chunk (hi+lo, 8KB each), swizzled
            const uint4* shi = (const uint4*)(g_Bhi + ch * 64 * CDIM);
            const uint4* slo = (const uint4*)(g_Blo + ch * 64 * CDIM);
            #pragma unroll
            for (int t = 0; t < 2; t++) {
                int i = tid + t * 256;                // 512 16B units each
                int row = i >> 3, cu = (i & 7) * 16;
                int dst = row * 128 + (cu ^ ((row & 7) * 16));
                *(uint4*)(smc + OFF_B_HI + dst) = shi[i];
                *(uint4*)(smc + OFF_B_LO + dst) = slo[i];
            }
        }
        __syncthreads();

        #pragma unroll
        for (int jp = 0; jp < 4; jp++) {          // j-pair: 16 codes
            float c00 = 0.f, c01 = 0.f, c02 = 0.f, c03 = 0.f;  // tile 0
            float c10 = 0.f, c11 = 0.f, c12 = 0.f, c13 = 0.f;  // tile 1
            const int rr = jp * 16 + btile * 8 + brow;
            #pragma unroll
            for (int ks = 0; ks < 4; ks++) {
                int col = (ks * 32 + bkhalf) ^ ((rr & 7) * 16);
                uint32_t h0, h1, h2, h3, l0, l1, l2, l3;
                ldsm_x4(h0, h1, h2, h3, sb + OFF_B_HI + rr * 128 + col);
                ldsm_x4(l0, l1, l2, l3, sb + OFF_B_LO + rr * 128 + col);
                mma_bf16(c00, c01, c02, c03, Ah[ks][0], Ah[ks][1], Ah[ks][2], Ah[ks][3], h0, h1);
                mma_bf16(c00, c01, c02, c03, Ah[ks][0], Ah[ks][1], Ah[ks][2], Ah[ks][3], l0, l1);
                mma_bf16(c10, c11, c12, c13, Ah[ks][0], Ah[ks][1], Ah[ks][2], Ah[ks][3], h2, h3);
                mma_bf16(c10, c11, c12, c13, Ah[ks][0], Ah[ks][1], Ah[ks][2], Ah[ks][3], l2, l3);
            }
            const int k0 = ch * 64 + jp * 16 + 2 * (lane & 3);
            float e0, e1, f0, f1;
            asm("ld.shared.v2.f32 {%0,%1}, [%2];"
                : "=f"(e0), "=f"(e1) : "r"(sb + OFF_EN2 + k0 * 4));
            asm("ld.shared.v2.f32 {%0,%1}, [%2];"
                : "=f"(f0), "=f"(f1) : "r"(sb + OFF_EN2 + (k0 + 8) * 4));
            ins3(encd(c00 + e0, k0),     m1a, m2a, m3a);
            ins3(encd(c01 + e1, k0 + 1), m1a, m2a, m3a);
            ins3(encd(c02 + e0, k0),     m1b, m2b, m3b);
            ins3(encd(c03 + e1, k0 + 1), m1b, m2b, m3b);
            ins3(encd(c10 + f0, k0 + 8), m1a, m2a, m3a);
            ins3(encd(c11 + f1, k0 + 9), m1a, m2a, m3a);
            ins3(encd(c12 + f0, k0 + 8), m1b, m2b, m3b);
            ins3(encd(c13 + f1, k0 + 9), m1b, m2b, m3b);
        }
    }

    // ---- merge triples across the 4 lanes sharing each accum row ----
    #pragma unroll
    for (int off = 1; off <= 2; off <<= 1) {
        float a1 = __shfl_xor_sync(0xffffffffu, m1a, off);
        float a2 = __shfl_xor_sync(0xffffffffu, m2a, off);
        float a3 = __shfl_xor_sync(0xffffffffu, m3a, off);
        ins3(a1, m1a, m2a, m3a); ins3(a2, m1a, m2a, m3a); ins3(a3, m1a, m2a, m3a);
        float b1 = __shfl_xor_sync(0xffffffffu, m1b, off);
        float b2 = __shfl_xor_sync(0xffffffffu, m2b, off);
        float b3 = __shfl_xor_sync(0xffffffffu, m3b, off);
        ins3(b1, m1b, m2b, m3b); ins3(b2, m1b, m2b, m3b); ins3(b3, m1b, m2b, m3b);
    }
    if ((lane & 3) == 0) {
        int r0 = 16 * wid + (lane >> 2);
        topv[r0 * 3 + 0] = m1a; topv[r0 * 3 + 1] = m2a; topv[r0 * 3 + 2] = m3a;
        int r1 = r0 + 8;
        topv[r1 * 3 + 0] = m1b; topv[r1 * 3 + 1] = m2b; topv[r1 * 3 + 2] = m3b;
    }
    __syncthreads();

    // ---- per-pixel epilogue (threads 0..127) ----
    float lossLocal = 0.0f;
    if (tid < 128) {
        const int p = pbase + tid;
        const float* xp = in + (p >> 12) * CHW + (p & (HWSZ - 1));
        float t1 = topv[tid * 3 + 0], t2 = topv[tid * 3 + 1], t3 = topv[tid * 3 + 2];
        int   j1 = decd(t1), j2 = decd(t2);

        int win;
        if (t2 - t1 >= EPS) {
            win = j1;                         // certified
        } else if (t3 - t1 >= EPS) {          // winner in {j1, j2}: exact compare
            float d1 = exact_dist(xp, emb, en2s[j1], j1);
            float d2 = exact_dist(xp, emb, en2s[j2], j2);
            win = (d2 < d1 || (d2 == d1 && j2 < j1)) ? j2 : j1;
        } else {
            win = -1;                         // rare: full exact scan
        }
        unsigned m = __ballot_sync(0xffffffffu, win < 0);
        while (m) {
            int src = __ffs(m) - 1; m &= m - 1;
            int pp = __shfl_sync(0xffffffffu, p, src);
            const float* xq = in + (pp >> 12) * CHW + (pp & (HWSZ - 1));
            float bd = 3.4e38f; int bi = 0;
            for (int kk = lane; kk < KCODES; kk += 32) {
                float dv = exact_dist(xq, emb, en2s[kk], kk);
                if (dv < bd || (dv == bd && kk < bi)) { bd = dv; bi = kk; }
            }
            #pragma unroll
            for (int o = 16; o; o >>= 1) {
                float od = __shfl_xor_sync(0xffffffffu, bd, o);
                int   oi = __shfl_xor_sync(0xffffffffu, bi, o);
                if (od < bd || (od == bd && oi < bi)) { bd = od; bi = oi; }
            }
            if (lane == src) win = bi;
        }

        atomicAdd(&histS[win], 1);
        out[OUT_IDX_OFF + p] = (float)win;
        const float4* qr = (const float4*)(emb + (win << 6));
        float* op = out + (p >> 12) * CHW + (p & (HWSZ - 1));
        #pragma unroll
        for (int c4 = 0; c4 < 16; c4++) {
            float4 q4 = qr[c4];
            float x0 = xp[(c4 * 4 + 0) * HWSZ];
            float x1 = xp[(c4 * 4 + 1) * HWSZ];
            float x2 = xp[(c4 * 4 + 2) * HWSZ];
            float x3 = xp[(c4 * 4 + 3) * HWSZ];
            op[(c4 * 4 + 0) * HWSZ] = q4.x;
            op[(c4 * 4 + 1) * HWSZ] = q4.y;
            op[(c4 * 4 + 2) * HWSZ] = q4.z;
            op[(c4 * 4 + 3) * HWSZ] = q4.w;
            float e0 = q4.x - x0, e1 = q4.y - x1, e2 = q4.z - x2, e3 = q4.w - x3;
            lossLocal += e0 * e0 + e1 * e1 + e2 * e2 + e3 * e3;
        }
        #pragma unroll
        for (int o = 16; o; o >>= 1)
            lossLocal += __shfl_xor_sync(0xffffffffu, lossLocal, o);
        if (lane == 0) ((float*)(smc + OFF_WS))[wid] = lossLocal;
    }
    __syncthreads();
    if (tid == 0) {
        float* ws = (float*)(smc + OFF_WS);
        g_part[blockIdx.x] = (ws[0] + ws[1]) + (ws[2] + ws[3]);
    }
    atomicAdd(&g_hist[tid],       histS[tid]);
    atomicAdd(&g_hist[tid + 256], histS[tid + 256]);
}

// ---------------- final: scalars ----------------
extern "C" __global__ void vq_final(const float* __restrict__ w,
                                    float* __restrict__ out)
{
    __shared__ float red[KCODES];
    const int t = threadIdx.x;

    float pv = (float)g_hist[t] * (1.0f / (float)N_PIX);
    red[t] = pv * logf(pv + 1e-10f);
    __syncthreads();
    #pragma unroll
    for (int s = KCODES / 2; s > 0; s >>= 1) {
        if (t < s) red[t] += red[t + s];
        __syncthreads();
    }
    float perp = 0.0f;
    if (t == 0) perp = expf(-red[0]);
    __syncthreads();

    red[t] = (w[t] >= 0.01f) ? 1.0f : 0.0f;
    __syncthreads();
    #pragma unroll
    for (int s = KCODES / 2; s > 0; s >>= 1) {
        if (t < s) red[t] += red[t + s];
        __syncthreads();
    }
    float act = 0.0f;
    if (t == 0) act = red[0];
    __syncthreads();

    red[t] = g_part[t];
    __syncthreads();
    #pragma unroll
    for (int s = KCODES / 2; s > 0; s >>= 1) {
        if (t < s) red[t] += red[t + s];
        __syncthreads();
    }
    if (t == 0) {
        out[OUT_LOSS_OFF] = red[0] * (1.0f / ((float)N_PIX * (float)CDIM));
        out[OUT_PERP_OFF] = perp;
        out[OUT_ACT_OFF]  = act;
    }
}

extern "C" void kernel_launch(void* const* d_in, const int* in_sizes, int n_in,
                              void* d_out, int out_size)
{
    const float* in  = (const float*)d_in[0];
    const float* emb = (const float*)d_in[1];
    const float* w   = (const float*)d_in[2];
    float* out = (float*)d_out;

    cudaFuncSetAttribute(vq_main, cudaFuncAttributeMaxDynamicSharedMemorySize,
                         SMEM_MAIN);

    vq_prep<<<128, 256>>>(emb);
    vq_main<<<NBLK, 256, SMEM_MAIN>>>(in, emb, out);
    vq_final<<<1, KCODES>>>(w, out);
}

// round 6
// speedup vs baseline: 6.3206x; 6.3206x over previous
#include <cuda_runtime.h>
#include <cuda_bf16.h>
#include <cstdint>

// ---------------- problem constants ----------------
#define N_PIX   65536
#define CDIM    64
#define KCODES  512
#define HWSZ    4096
#define CHW     (CDIM * HWSZ)

#define OUT_Q_ELEMS  (N_PIX * CDIM)
#define OUT_LOSS_OFF OUT_Q_ELEMS
#define OUT_PERP_OFF (OUT_Q_ELEMS + 1)
#define OUT_ACT_OFF  (OUT_Q_ELEMS + 2)
#define OUT_IDX_OFF  (OUT_Q_ELEMS + 3)

#define TILE_P  128
#define NBLK    (N_PIX / TILE_P)       // 512
#define NCHUNK  8                      // 8 x 64 codes
#define EPS     0.125f                 // cert window: > 2*(3-term mma err + enc err)

// ---------------- device scratch ----------------
__device__ __align__(16) uint16_t g_Bhi[KCODES * CDIM];
__device__ __align__(16) uint16_t g_Blo[KCODES * CDIM];
__device__ __align__(16) float    g_en2[KCODES];
__device__ int   g_hist[KCODES];
__device__ float g_part[NBLK];

// ---------------- smem layout ----------------
#define OFF_A_HI  0          // 16384  bf16(-2x) hi, 128 rows x 128B swizzled
#define OFF_A_LO  16384      // 16384  bf16 lo residual
#define OFF_B_HI  32768      // 8192
#define OFF_B_LO  40960      // 8192
#define OFF_EN2   49152      // 2048
#define OFF_TOPV  51200      // 1536   128 rows x 3 floats (idx packed in mantissa)
#define OFF_HIST  52736      // 2048
#define OFF_WS    54784      // 128
#define SMEM_MAIN 54912

// ---------------- PTX helpers (compute_103-legal only) ----------------
__device__ __forceinline__ uint32_t s2u(const void* p) {
    uint32_t a;
    asm("{ .reg .u64 t; cvta.to.shared.u64 t, %1; cvt.u32.u64 %0, t; }"
        : "=r"(a) : "l"(p));
    return a;
}
__device__ __forceinline__ void ldsm_x4(uint32_t& r0, uint32_t& r1,
                                        uint32_t& r2, uint32_t& r3, uint32_t a) {
    asm volatile("ldmatrix.sync.aligned.m8n8.x4.shared.b16 {%0,%1,%2,%3}, [%4];"
                 : "=r"(r0), "=r"(r1), "=r"(r2), "=r"(r3) : "r"(a));
}
__device__ __forceinline__ void mma_bf16(float& c0, float& c1, float& c2, float& c3,
                                         uint32_t a0, uint32_t a1, uint32_t a2, uint32_t a3,
                                         uint32_t b0, uint32_t b1) {
    asm volatile(
        "mma.sync.aligned.m16n8k16.row.col.f32.bf16.bf16.f32 "
        "{%0,%1,%2,%3}, {%4,%5,%6,%7}, {%8,%9}, {%0,%1,%2,%3};"
        : "+f"(c0), "+f"(c1), "+f"(c2), "+f"(c3)
        : "r"(a0), "r"(a1), "r"(a2), "r"(a3), "r"(b0), "r"(b1));
}

// pack code index into 9 low mantissa bits; fmin then carries the index for free
__device__ __forceinline__ float encd(float d, int k) {
    return __uint_as_float((__float_as_uint(d) & ~511u) | (uint32_t)k);
}
__device__ __forceinline__ int decd(float v) {
    return (int)(__float_as_uint(v) & 511u);
}
// branchless sorted-triple insert: 5 FMNMX, no predicates
__device__ __forceinline__ void ins3(float d, float& m1, float& m2, float& m3) {
    float t  = fmaxf(m1, d);
    m1 = fminf(m1, d);
    float t2 = fmaxf(m2, t);
    m2 = fminf(m2, t);
    m3 = fminf(m3, t2);
}

__device__ __forceinline__ float exact_dist(const float* __restrict__ xp,
                                            const float* __restrict__ emb,
                                            float en2v, int k) {
    const float4* er = (const float4*)(emb + (k << 6));
    float s0 = 0.f, s1 = 0.f, s2 = 0.f, s3 = 0.f;
    #pragma unroll
    for (int c4 = 0; c4 < 16; c4++) {
        float4 e4 = er[c4];
        s0 = fmaf(xp[(c4 * 4 + 0) * HWSZ], e4.x, s0);
        s1 = fmaf(xp[(c4 * 4 + 1) * HWSZ], e4.y, s1);
        s2 = fmaf(xp[(c4 * 4 + 2) * HWSZ], e4.z, s2);
        s3 = fmaf(xp[(c4 * 4 + 3) * HWSZ], e4.w, s3);
    }
    return fmaf(-2.0f, (s0 + s1) + (s2 + s3), en2v);
}

// ---------------- prep: bf16-split codebook + parallel en2 + zero hist ----------------
extern "C" __global__ void vq_prep(const float* __restrict__ emb) {
    __shared__ float ws[8];
    const int tid = threadIdx.x;
    const int idx = blockIdx.x * 256 + tid;           // 128 blocks x 256 = 32768
    float e = emb[idx];
    __nv_bfloat16 hi = __float2bfloat16(e);
    __nv_bfloat16 lo = __float2bfloat16(e - __bfloat162float(hi));
    g_Bhi[idx] = __bfloat16_as_ushort(hi);
    g_Blo[idx] = __bfloat16_as_ushort(lo);
    // en2: block covers 4 codes (64 ch each = 2 warps); shuffle-reduce
    float v = e * e;
    #pragma unroll
    for (int o = 16; o; o >>= 1) v += __shfl_xor_sync(0xffffffffu, v, o);
    if ((tid & 31) == 0) ws[tid >> 5] = v;
    __syncthreads();
    if (tid < 4) g_en2[blockIdx.x * 4 + tid] = ws[2 * tid] + ws[2 * tid + 1];
    if (blockIdx.x < 2) g_hist[blockIdx.x * 256 + tid] = 0;
}

// ---------------- main ----------------
extern "C" __global__ void __launch_bounds__(256, 4)
vq_main(const float* __restrict__ in, const float* __restrict__ emb,
        float* __restrict__ out)
{
    extern __shared__ char smc[];
    const uint32_t sb = s2u(smc);
    const int tid  = threadIdx.x;
    const int lane = tid & 31;
    const int wid  = tid >> 5;

    int*   histS = (int*)(smc + OFF_HIST);
    float* en2s  = (float*)(smc + OFF_EN2);
    float* topv  = (float*)(smc + OFF_TOPV);

    histS[tid] = 0; histS[tid + 256] = 0;
    if (tid < 128) ((float4*)en2s)[tid] = ((const float4*)g_en2)[tid];

    const int pbase = blockIdx.x * TILE_P;

    // ---- stage A: bf16(-2x) hi + lo residual, 128B swizzled rows ----
    {
        const int px = tid & 127;
        const int cb = (tid >> 7) * 32;
        const int p  = pbase + px;
        const float* xp = in + (p >> 12) * CHW + (p & (HWSZ - 1));
        #pragma unroll
        for (int c = cb; c < cb + 32; c += 2) {
            float x0 = -2.0f * xp[c * HWSZ];
            float x1 = -2.0f * xp[(c + 1) * HWSZ];
            __nv_bfloat16 h0 = __float2bfloat16(x0);
            __nv_bfloat16 h1 = __float2bfloat16(x1);
            __nv_bfloat16 l0 = __float2bfloat16(x0 - __bfloat162float(h0));
            __nv_bfloat16 l1 = __float2bfloat16(x1 - __bfloat162float(h1));
            uint32_t hp = (uint32_t)__bfloat16_as_ushort(h0) |
                          ((uint32_t)__bfloat16_as_ushort(h1) << 16);
            uint32_t lp = (uint32_t)__bfloat16_as_ushort(l0) |
                          ((uint32_t)__bfloat16_as_ushort(l1) << 16);
            int col = (c * 2) ^ ((px & 7) * 16);
            *(uint32_t*)(smc + OFF_A_HI + px * 128 + col) = hp;
            *(uint32_t*)(smc + OFF_A_LO + px * 128 + col) = lp;
        }
    }
    __syncthreads();

    // ---- resident A fragments (hi + lo): warp owns pixel rows 16*wid..+15 ----
    uint32_t Ah[4][4], Al[4][4];
    {
        const int mtx = lane >> 3;
        const int r   = 16 * wid + (mtx & 1) * 8 + (lane & 7);
        const int kh  = (mtx >> 1) * 16;
        #pragma unroll
        for (int ks = 0; ks < 4; ks++) {
            int col = (ks * 32 + kh) ^ ((r & 7) * 16);
            ldsm_x4(Ah[ks][0], Ah[ks][1], Ah[ks][2], Ah[ks][3],
                    sb + OFF_A_HI + r * 128 + col);
            ldsm_x4(Al[ks][0], Al[ks][1], Al[ks][2], Al[ks][3],
                    sb + OFF_A_LO + r * 128 + col);
        }
    }

    // ---- sweep: 8 chunks x 4 j-pairs; 3-term MMA; top-3 via FMNMX ----
    float m1a = 3.4e38f, m2a = 3.4e38f, m3a = 3.4e38f;   // row r
    float m1b = 3.4e38f, m2b = 3.4e38f, m3b = 3.4e38f;   // row r+8

    const int btile  = (lane >> 4) & 1;
    const int bkhalf = ((lane >> 3) & 1) * 16;
    const int brow   = lane & 7;

    for (int ch = 0; ch < NCHUNK; ch++) {
        __syncthreads();
        {   // stage B chunk (hi+lo, 8KB each), swizzled
            const uint4* shi = (const uint4*)(g_Bhi + ch * 64 * CDIM);
            const uint4* slo = (const uint4*)(g_Blo + ch * 64 * CDIM);
            #pragma unroll
            for (int t = 0; t < 2; t++) {
                int i = tid + t * 256;                // 512 16B units each
                int row = i >> 3, cu = (i & 7) * 16;
                int dst = row * 128 + (cu ^ ((row & 7) * 16));
                *(uint4*)(smc + OFF_B_HI + dst) = shi[i];
                *(uint4*)(smc + OFF_B_LO + dst) = slo[i];
            }
        }
        __syncthreads();

        #pragma unroll
        for (int jp = 0; jp < 4; jp++) {          // j-pair: 16 codes
            float c00 = 0.f, c01 = 0.f, c02 = 0.f, c03 = 0.f;  // tile 0
            float c10 = 0.f, c11 = 0.f, c12 = 0.f, c13 = 0.f;  // tile 1
            const int rr = jp * 16 + btile * 8 + brow;
            #pragma unroll
            for (int ks = 0; ks < 4; ks++) {
                int col = (ks * 32 + bkhalf) ^ ((rr & 7) * 16);
                uint32_t h0, h1, h2, h3, l0, l1, l2, l3;
                ldsm_x4(h0, h1, h2, h3, sb + OFF_B_HI + rr * 128 + col);
                ldsm_x4(l0, l1, l2, l3, sb + OFF_B_LO + rr * 128 + col);
                mma_bf16(c00, c01, c02, c03, Ah[ks][0], Ah[ks][1], Ah[ks][2], Ah[ks][3], h0, h1);
                mma_bf16(c00, c01, c02, c03, Al[ks][0], Al[ks][1], Al[ks][2], Al[ks][3], h0, h1);
                mma_bf16(c00, c01, c02, c03, Ah[ks][0], Ah[ks][1], Ah[ks][2], Ah[ks][3], l0, l1);
                mma_bf16(c10, c11, c12, c13, Ah[ks][0], Ah[ks][1], Ah[ks][2], Ah[ks][3], h2, h3);
                mma_bf16(c10, c11, c12, c13, Al[ks][0], Al[ks][1], Al[ks][2], Al[ks][3], h2, h3);
                mma_bf16(c10, c11, c12, c13, Ah[ks][0], Ah[ks][1], Ah[ks][2], Ah[ks][3], l2, l3);
            }
            const int k0 = ch * 64 + jp * 16 + 2 * (lane & 3);
            float e0, e1, f0, f1;
            asm("ld.shared.v2.f32 {%0,%1}, [%2];"
                : "=f"(e0), "=f"(e1) : "r"(sb + OFF_EN2 + k0 * 4));
            asm("ld.shared.v2.f32 {%0,%1}, [%2];"
                : "=f"(f0), "=f"(f1) : "r"(sb + OFF_EN2 + (k0 + 8) * 4));
            ins3(encd(c00 + e0, k0),     m1a, m2a, m3a);
            ins3(encd(c01 + e1, k0 + 1), m1a, m2a, m3a);
            ins3(encd(c02 + e0, k0),     m1b, m2b, m3b);
            ins3(encd(c03 + e1, k0 + 1), m1b, m2b, m3b);
            ins3(encd(c10 + f0, k0 + 8), m1a, m2a, m3a);
            ins3(encd(c11 + f1, k0 + 9), m1a, m2a, m3a);
            ins3(encd(c12 + f0, k0 + 8), m1b, m2b, m3b);
            ins3(encd(c13 + f1, k0 + 9), m1b, m2b, m3b);
        }
    }

    // ---- merge triples across the 4 lanes sharing each accum row ----
    #pragma unroll
    for (int off = 1; off <= 2; off <<= 1) {
        float a1 = __shfl_xor_sync(0xffffffffu, m1a, off);
        float a2 = __shfl_xor_sync(0xffffffffu, m2a, off);
        float a3 = __shfl_xor_sync(0xffffffffu, m3a, off);
        ins3(a1, m1a, m2a, m3a); ins3(a2, m1a, m2a, m3a); ins3(a3, m1a, m2a, m3a);
        float b1 = __shfl_xor_sync(0xffffffffu, m1b, off);
        float b2 = __shfl_xor_sync(0xffffffffu, m2b, off);
        float b3 = __shfl_xor_sync(0xffffffffu, m3b, off);
        ins3(b1, m1b, m2b, m3b); ins3(b2, m1b, m2b, m3b); ins3(b3, m1b, m2b, m3b);
    }
    if ((lane & 3) == 0) {
        int r0 = 16 * wid + (lane >> 2);
        topv[r0 * 3 + 0] = m1a; topv[r0 * 3 + 1] = m2a; topv[r0 * 3 + 2] = m3a;
        int r1 = r0 + 8;
        topv[r1 * 3 + 0] = m1b; topv[r1 * 3 + 1] = m2b; topv[r1 * 3 + 2] = m3b;
    }
    __syncthreads();

    // ---- per-pixel epilogue (threads 0..127) ----
    float lossLocal = 0.0f;
    if (tid < 128) {
        const int p = pbase + tid;
        const float* xp = in + (p >> 12) * CHW + (p & (HWSZ - 1));
        float t1 = topv[tid * 3 + 0], t2 = topv[tid * 3 + 1], t3 = topv[tid * 3 + 2];
        int   j1 = decd(t1), j2 = decd(t2);

        int win;
        if (t2 - t1 >= EPS) {
            win = j1;                         // certified
        } else if (t3 - t1 >= EPS) {          // winner in {j1, j2}: exact compare
            float d1 = exact_dist(xp, emb, en2s[j1], j1);
            float d2 = exact_dist(xp, emb, en2s[j2], j2);
            win = (d2 < d1 || (d2 == d1 && j2 < j1)) ? j2 : j1;
        } else {
            win = -1;                         // rare: full exact scan
        }
        unsigned m = __ballot_sync(0xffffffffu, win < 0);
        while (m) {
            int src = __ffs(m) - 1; m &= m - 1;
            int pp = __shfl_sync(0xffffffffu, p, src);
            const float* xq = in + (pp >> 12) * CHW + (pp & (HWSZ - 1));
            float bd = 3.4e38f; int bi = 0;
            for (int kk = lane; kk < KCODES; kk += 32) {
                float dv = exact_dist(xq, emb, en2s[kk], kk);
                if (dv < bd || (dv == bd && kk < bi)) { bd = dv; bi = kk; }
            }
            #pragma unroll
            for (int o = 16; o; o >>= 1) {
                float od = __shfl_xor_sync(0xffffffffu, bd, o);
                int   oi = __shfl_xor_sync(0xffffffffu, bi, o);
                if (od < bd || (od == bd && oi < bi)) { bd = od; bi = oi; }
            }
            if (lane == src) win = bi;
        }

        atomicAdd(&histS[win], 1);
        out[OUT_IDX_OFF + p] = (float)win;
        const float4* qr = (const float4*)(emb + (win << 6));
        float* op = out + (p >> 12) * CHW + (p & (HWSZ - 1));
        #pragma unroll
        for (int c4 = 0; c4 < 16; c4++) {
            float4 q4 = qr[c4];
            float x0 = xp[(c4 * 4 + 0) * HWSZ];
            float x1 = xp[(c4 * 4 + 1) * HWSZ];
            float x2 = xp[(c4 * 4 + 2) * HWSZ];
            float x3 = xp[(c4 * 4 + 3) * HWSZ];
            op[(c4 * 4 + 0) * HWSZ] = q4.x;
            op[(c4 * 4 + 1) * HWSZ] = q4.y;
            op[(c4 * 4 + 2) * HWSZ] = q4.z;
            op[(c4 * 4 + 3) * HWSZ] = q4.w;
            float e0 = q4.x - x0, e1 = q4.y - x1, e2 = q4.z - x2, e3 = q4.w - x3;
            lossLocal += e0 * e0 + e1 * e1 + e2 * e2 + e3 * e3;
        }
        #pragma unroll
        for (int o = 16; o; o >>= 1)
            lossLocal += __shfl_xor_sync(0xffffffffu, lossLocal, o);
        if (lane == 0) ((float*)(smc + OFF_WS))[wid] = lossLocal;
    }
    __syncthreads();
    if (tid == 0) {
        float* ws = (float*)(smc + OFF_WS);
        g_part[blockIdx.x] = (ws[0] + ws[1]) + (ws[2] + ws[3]);
    }
    atomicAdd(&g_hist[tid],       histS[tid]);
    atomicAdd(&g_hist[tid + 256], histS[tid + 256]);
}

// ---------------- final: scalars ----------------
extern "C" __global__ void vq_final(const float* __restrict__ w,
                                    float* __restrict__ out)
{
    __shared__ float red[KCODES];
    const int t = threadIdx.x;

    float pv = (float)g_hist[t] * (1.0f / (float)N_PIX);
    red[t] = pv * logf(pv + 1e-10f);
    __syncthreads();
    #pragma unroll
    for (int s = KCODES / 2; s > 0; s >>= 1) {
        if (t < s) red[t] += red[t + s];
        __syncthreads();
    }
    float perp = 0.0f;
    if (t == 0) perp = expf(-red[0]);
    __syncthreads();

    red[t] = (w[t] >= 0.01f) ? 1.0f : 0.0f;
    __syncthreads();
    #pragma unroll
    for (int s = KCODES / 2; s > 0; s >>= 1) {
        if (t < s) red[t] += red[t + s];
        __syncthreads();
    }
    float act = 0.0f;
    if (t == 0) act = red[0];
    __syncthreads();

    red[t] = g_part[t];
    __syncthreads();
    #pragma unroll
    for (int s = KCODES / 2; s > 0; s >>= 1) {
        if (t < s) red[t] += red[t + s];
        __syncthreads();
    }
    if (t == 0) {
        out[OUT_LOSS_OFF] = red[0] * (1.0f / ((float)N_PIX * (float)CDIM));
        out[OUT_PERP_OFF] = perp;
        out[OUT_ACT_OFF]  = act;
    }
}

extern "C" void kernel_launch(void* const* d_in, const int* in_sizes, int n_in,
                              void* d_out, int out_size)
{
    const float* in  = (const float*)d_in[0];
    const float* emb = (const float*)d_in[1];
    const float* w   = (const float*)d_in[2];
    float* out = (float*)d_out;

    cudaFuncSetAttribute(vq_main, cudaFuncAttributeMaxDynamicSharedMemorySize,
                         SMEM_MAIN);

    vq_prep<<<128, 256>>>(emb);
    vq_main<<<NBLK, 256, SMEM_MAIN>>>(in, emb, out);
    vq_final<<<1, KCODES>>>(w, out);
}